// round 5
// baseline (speedup 1.0000x reference)
#include <cuda_runtime.h>

// TT-linear: y = x @ W^T + bias
//   c0: [1,32(o0),32(i0),4(r1)]  c1: [4(r1),16(o1),16(i1),4(r2)]  c2: [4(r2),16(o2),16(i2),1]
//
// Kernel 1: grid 512 = (token, i0-quarter), 256 thr = (o1,o2); 8 i0 per CTA (4*8 = 32).
//   per i0: step1 A[i1,o2,r2] (i2-pair-packed fma2, x from smem, no shfl)
//           step2 B[r1] (r2-pair-packed, 8 accum chains, LDS.128-native operands)
//           step3 y[o0-pairs] += B (o0-pair-packed)
//   partials -> 16MB scratch.  Kernel 2: out = sum(4 partials) + bias (grid 256).

#define THREADS 256

__device__ float g_scratch[4u * 128u * 8192u];  // 16 MB partials

typedef unsigned long long u64;

__device__ __forceinline__ u64 pk2(float lo, float hi) {
    u64 r;
    asm("mov.b64 %0, {%1, %2};" : "=l"(r) : "f"(lo), "f"(hi));
    return r;
}
__device__ __forceinline__ void unpk(u64 v, float& lo, float& hi) {
    asm("mov.b64 {%0, %1}, %2;" : "=f"(lo), "=f"(hi) : "l"(v));
}
__device__ __forceinline__ u64 fma2(u64 a, u64 b, u64 c) {
    u64 d;
    asm("fma.rn.f32x2 %0, %1, %2, %3;" : "=l"(d) : "l"(a), "l"(b), "l"(c));
    return d;
}
__device__ __forceinline__ float hadd(u64 v) {
    float lo, hi;
    unpk(v, lo, hi);
    return lo + hi;
}

__global__ __launch_bounds__(THREADS, 2)
void tt_partial_kernel(const float* __restrict__ x,
                       const float* __restrict__ g0,
                       const float* __restrict__ g1,
                       const float* __restrict__ g2)
{
    __shared__ __align__(16) float sc0[1024];    // [it 0..7][r1][o0]   (this quarter's 8 i0)
    __shared__ __align__(16) float sc1[4096];    // [o1][i1][r1][r2]
    __shared__ __align__(16) float sc2[1024];    // [r2][o2][i2]        (= g2 layout)
    __shared__ __align__(16) float sA[2][1024];  // [i1][o2][r2]
    __shared__ __align__(16) float sX[2][256];   // raw x slice

    const int tid     = threadIdx.x;
    const int token   = blockIdx.x & 127;
    const int quarter = blockIdx.x >> 7;
    const int o1      = tid >> 4;        // doubles as i1 in step 1
    const int o2      = tid & 15;
    const int i0base  = quarter * 8;     // 8 i0 values per CTA: 4 quarters x 8 = 32

    // ---- core relayout into smem ----
    // sc0[it*128 + r1*32 + o0] <- g0[(o0*32 + i0)*4 + r1], i0 = i0base+it, it=0..7
    for (int idx = tid; idx < 1024; idx += THREADS) {
        int o0 = idx & 31, r1 = (idx >> 5) & 3, it = idx >> 7;
        sc0[idx] = g0[(o0 * 32 + i0base + it) * 4 + r1];
    }
    // sc1[((o1*16+i1)*4 + r1)*4 + r2] <- g1[((r1*16+o1)*16+i1)*4 + r2]
    for (int idx = tid; idx < 4096; idx += THREADS) {
        int r2 = idx & 3, r1 = (idx >> 2) & 3, i1 = (idx >> 4) & 15, o1g = idx >> 8;
        sc1[idx] = g1[((r1 * 16 + o1g) * 16 + i1) * 4 + r2];
    }
    // sc2 = g2 verbatim: [r2][o2][i2]
    for (int idx = tid; idx < 1024; idx += THREADS) sc2[idx] = g2[idx];

    const float* xrow = x + token * 8192;
    sX[0][tid] = xrow[i0base * 256 + tid];

    u64 yp[16];                          // y[32] as packed o0 pairs
    #pragma unroll
    for (int i = 0; i < 16; i++) yp[i] = 0ull;

    __syncthreads();

    #pragma unroll
    for (int it = 0; it < 8; it++) {
        const int i0 = i0base + it;

        // prefetch next x slice (gmem -> reg), staged to smem before the sync
        float xnext = 0.f;
        if (it < 7) xnext = xrow[(i0 + 1) * 256 + tid];

        // ---- step 1: A[i1][o2][r2] = sum_i2 x[i1,i2]*c2[r2,o2,i2]   (i1 = o1 role)
        {
            const ulonglong2* xp = reinterpret_cast<const ulonglong2*>(&sX[it & 1][o1 * 16]);
            ulonglong2 xv0 = xp[0], xv1 = xp[1], xv2 = xp[2], xv3 = xp[3];
            u64 xu[8] = { xv0.x, xv0.y, xv1.x, xv1.y, xv2.x, xv2.y, xv3.x, xv3.y };
            float a[4];
            #pragma unroll
            for (int r2 = 0; r2 < 4; r2++) {
                const ulonglong2* cp = reinterpret_cast<const ulonglong2*>(
                    &sc2[r2 * 256 + o2 * 16]);
                ulonglong2 c0v = cp[0], c1v = cp[1], c2v = cp[2], c3v = cp[3];
                u64 acc = fma2(xu[0], c0v.x, 0ull);
                acc = fma2(xu[1], c0v.y, acc);
                acc = fma2(xu[2], c1v.x, acc);
                acc = fma2(xu[3], c1v.y, acc);
                acc = fma2(xu[4], c2v.x, acc);
                acc = fma2(xu[5], c2v.y, acc);
                acc = fma2(xu[6], c3v.x, acc);
                acc = fma2(xu[7], c3v.y, acc);
                a[r2] = hadd(acc);
            }
            ulonglong2 st;
            st.x = pk2(a[0], a[1]);
            st.y = pk2(a[2], a[3]);
            *reinterpret_cast<ulonglong2*>(&sA[it & 1][(o1 * 16 + o2) * 4]) = st;
        }
        sX[(it + 1) & 1][tid] = xnext;
        __syncthreads();

        // ---- step 2: B[r1] = sum_{i1,r2} A[i1,o2,r2]*c1[r1,o1,i1,r2]
        u64 acc2[4][2];
        #pragma unroll
        for (int r1 = 0; r1 < 4; r1++) { acc2[r1][0] = 0ull; acc2[r1][1] = 0ull; }
        const float* A = sA[it & 1];
        #pragma unroll
        for (int i1 = 0; i1 < 16; i1++) {
            const ulonglong2 av = *reinterpret_cast<const ulonglong2*>(
                &A[(i1 * 16 + o2) * 4]);                 // (r2 0,1),(r2 2,3)
            const ulonglong2* cp = reinterpret_cast<const ulonglong2*>(
                &sc1[(o1 * 16 + i1) * 16]);              // [r1][(r2 0,1),(r2 2,3)]
            #pragma unroll
            for (int r1 = 0; r1 < 4; r1++) {
                ulonglong2 c = cp[r1];
                acc2[r1][0] = fma2(av.x, c.x, acc2[r1][0]);
                acc2[r1][1] = fma2(av.y, c.y, acc2[r1][1]);
            }
        }
        u64 bd[4];
        #pragma unroll
        for (int r1 = 0; r1 < 4; r1++) {
            float b = hadd(acc2[r1][0]) + hadd(acc2[r1][1]);
            bd[r1] = pk2(b, b);
        }

        // ---- step 3: y[o0-pair] += sum_r1 B[r1]*c0[i0,r1,o0]
        const ulonglong2* cq = reinterpret_cast<const ulonglong2*>(&sc0[it * 128]);
        #pragma unroll
        for (int q = 0; q < 8; q++) {
            #pragma unroll
            for (int r1 = 0; r1 < 4; r1++) {
                ulonglong2 c = cq[r1 * 8 + q];           // o0 = 4q..4q+3
                yp[2 * q]     = fma2(bd[r1], c.x, yp[2 * q]);
                yp[2 * q + 1] = fma2(bd[r1], c.y, yp[2 * q + 1]);
            }
        }
    }

    // ---- write partial (coalesced across threads) ----
    float* sp = g_scratch + ((size_t)(quarter * 128 + token) << 13);
    #pragma unroll
    for (int q = 0; q < 8; q++) {
        float f0, f1, f2, f3;
        unpk(yp[2 * q],     f0, f1);
        unpk(yp[2 * q + 1], f2, f3);
        sp[(4 * q + 0) * 256 + tid] = f0;
        sp[(4 * q + 1) * 256 + tid] = f1;
        sp[(4 * q + 2) * 256 + tid] = f2;
        sp[(4 * q + 3) * 256 + tid] = f3;
    }
}

__global__ __launch_bounds__(256)
void tt_reduce_kernel(const float* __restrict__ bias, float* __restrict__ out)
{
    // out = 262144 float4; grid 256 x 256 thr x 4 float4/thread, 16 loads in flight
    const int base = blockIdx.x * 1024 + threadIdx.x;    // max v = 261887 + 256*3... < 262144
    const float4* s = reinterpret_cast<const float4*>(g_scratch);
    float4 a0[4], a1[4], a2[4], a3[4];
    #pragma unroll
    for (int k = 0; k < 4; k++) {
        int v = base + k * 256;
        a0[k] = s[v];
        a1[k] = s[v + (1 << 18)];
        a2[k] = s[v + (2 << 18)];
        a3[k] = s[v + (3 << 18)];
    }
    #pragma unroll
    for (int k = 0; k < 4; k++) {
        int v = base + k * 256;
        float4 b4 = reinterpret_cast<const float4*>(bias)[v & 2047];
        float4 r;
        r.x = a0[k].x + a1[k].x + a2[k].x + a3[k].x + b4.x;
        r.y = a0[k].y + a1[k].y + a2[k].y + a3[k].y + b4.y;
        r.z = a0[k].z + a1[k].z + a2[k].z + a3[k].z + b4.z;
        r.w = a0[k].w + a1[k].w + a2[k].w + a3[k].w + b4.w;
        reinterpret_cast<float4*>(out)[v] = r;
    }
}

extern "C" void kernel_launch(void* const* d_in, const int* in_sizes, int n_in,
                              void* d_out, int out_size)
{
    const float* x    = (const float*)d_in[0];  // [128, 8192]
    const float* g0   = (const float*)d_in[1];  // [1,32,32,4]
    const float* g1   = (const float*)d_in[2];  // [4,16,16,4]
    const float* g2   = (const float*)d_in[3];  // [4,16,16,1]
    const float* bias = (const float*)d_in[4];  // [8192]
    float* out = (float*)d_out;                 // [128, 8192]

    tt_partial_kernel<<<512, THREADS>>>(x, g0, g1, g2);
    tt_reduce_kernel<<<256, 256>>>(bias, out);
}

// round 6
// speedup vs baseline: 1.4266x; 1.4266x over previous
#include <cuda_runtime.h>

// TT-linear: y = x @ W^T + bias
//   c0: [1,32(o0),32(i0),4(r1)]  c1: [4(r1),16(o1),16(i1),4(r2)]  c2: [4(r2),16(o2),16(i2),1]
//
// Kernel 1: grid 256 = (token, i0-half), 256 thr = (o1,o2); 16 i0 per CTA as 8 PAIRS.
//   Pair = two independent i0 streams interleaved between syncs (convoy breaking):
//     step1 both -> sync -> step2 both (shared c1 loads) + step3 both -> prefetch x -> sync
//   partials -> 8MB scratch.  Kernel 2: out = p0 + p1 + bias (grid 2048x128).

#define THREADS 256

__device__ float g_scratch[2u * 128u * 8192u];  // 8 MB partials

typedef unsigned long long u64;

__device__ __forceinline__ u64 pk2(float lo, float hi) {
    u64 r;
    asm("mov.b64 %0, {%1, %2};" : "=l"(r) : "f"(lo), "f"(hi));
    return r;
}
__device__ __forceinline__ void unpk(u64 v, float& lo, float& hi) {
    asm("mov.b64 {%0, %1}, %2;" : "=f"(lo), "=f"(hi) : "l"(v));
}
__device__ __forceinline__ u64 fma2(u64 a, u64 b, u64 c) {
    u64 d;
    asm("fma.rn.f32x2 %0, %1, %2, %3;" : "=l"(d) : "l"(a), "l"(b), "l"(c));
    return d;
}
__device__ __forceinline__ float hadd(u64 v) {
    float lo, hi;
    unpk(v, lo, hi);
    return lo + hi;
}

__global__ __launch_bounds__(THREADS, 2)
void tt_partial_kernel(const float* __restrict__ x,
                       const float* __restrict__ g0,
                       const float* __restrict__ g1,
                       const float* __restrict__ g2)
{
    __shared__ __align__(16) float sc0[2048];      // [it 0..15][r1][o0]
    __shared__ __align__(16) float sc1[4096];      // [o1][i1][r1][r2]
    __shared__ __align__(16) float sc2[1024];      // [r2][o2][i2]  (= g2 layout)
    __shared__ __align__(16) float sA[2][1024];    // pair slot a/b: [i1][o2][r2]
    __shared__ __align__(16) float sX[2][2][256];  // [pair parity][slice in pair][tid]

    const int tid    = threadIdx.x;
    const int token  = blockIdx.x & 127;
    const int half   = blockIdx.x >> 7;
    const int o1     = tid >> 4;          // doubles as i1 in step 1
    const int o2     = tid & 15;
    const int i0base = half * 16;         // 16 i0 per CTA: 2 halves x 16 = 32

    // ---- core relayout into smem ----
    for (int idx = tid; idx < 2048; idx += THREADS) {
        int o0 = idx & 31, r1 = (idx >> 5) & 3, it = idx >> 7;      // it = 0..15
        sc0[idx] = g0[(o0 * 32 + i0base + it) * 4 + r1];
    }
    for (int idx = tid; idx < 4096; idx += THREADS) {
        int r2 = idx & 3, r1 = (idx >> 2) & 3, i1 = (idx >> 4) & 15, o1g = idx >> 8;
        sc1[idx] = g1[((r1 * 16 + o1g) * 16 + i1) * 4 + r2];
    }
    for (int idx = tid; idx < 1024; idx += THREADS) sc2[idx] = g2[idx];

    const float* xrow = x + token * 8192;
    sX[0][0][tid] = xrow[(i0base + 0) * 256 + tid];
    sX[0][1][tid] = xrow[(i0base + 1) * 256 + tid];

    u64 yp[16];                           // y[32] as packed o0 pairs
    #pragma unroll
    for (int i = 0; i < 16; i++) yp[i] = 0ull;

    __syncthreads();

    for (int k = 0; k < 8; k++) {         // 8 pairs of i0
        const int p = k & 1;

        // prefetch next pair's x slices into registers early
        float xn0 = 0.f, xn1 = 0.f;
        if (k < 7) {
            xn0 = xrow[(i0base + 2 * k + 2) * 256 + tid];
            xn1 = xrow[(i0base + 2 * k + 3) * 256 + tid];
        }

        // ---- step 1 (both slices, shared c2 loads): A[i1][o2][r2] ----
        {
            const ulonglong2* xpa = reinterpret_cast<const ulonglong2*>(&sX[p][0][o1 * 16]);
            const ulonglong2* xpb = reinterpret_cast<const ulonglong2*>(&sX[p][1][o1 * 16]);
            ulonglong2 va0 = xpa[0], va1 = xpa[1], va2 = xpa[2], va3 = xpa[3];
            ulonglong2 vb0 = xpb[0], vb1 = xpb[1], vb2 = xpb[2], vb3 = xpb[3];
            u64 xa[8] = { va0.x, va0.y, va1.x, va1.y, va2.x, va2.y, va3.x, va3.y };
            u64 xb[8] = { vb0.x, vb0.y, vb1.x, vb1.y, vb2.x, vb2.y, vb3.x, vb3.y };
            float aa[4], ab[4];
            #pragma unroll
            for (int r2 = 0; r2 < 4; r2++) {
                const ulonglong2* cp = reinterpret_cast<const ulonglong2*>(
                    &sc2[r2 * 256 + o2 * 16]);
                ulonglong2 c0v = cp[0], c1v = cp[1], c2v = cp[2], c3v = cp[3];
                u64 acca = fma2(xa[0], c0v.x, 0ull);
                u64 accb = fma2(xb[0], c0v.x, 0ull);
                acca = fma2(xa[1], c0v.y, acca);  accb = fma2(xb[1], c0v.y, accb);
                acca = fma2(xa[2], c1v.x, acca);  accb = fma2(xb[2], c1v.x, accb);
                acca = fma2(xa[3], c1v.y, acca);  accb = fma2(xb[3], c1v.y, accb);
                acca = fma2(xa[4], c2v.x, acca);  accb = fma2(xb[4], c2v.x, accb);
                acca = fma2(xa[5], c2v.y, acca);  accb = fma2(xb[5], c2v.y, accb);
                acca = fma2(xa[6], c3v.x, acca);  accb = fma2(xb[6], c3v.x, accb);
                acca = fma2(xa[7], c3v.y, acca);  accb = fma2(xb[7], c3v.y, accb);
                aa[r2] = hadd(acca);
                ab[r2] = hadd(accb);
            }
            ulonglong2 sta, stb;
            sta.x = pk2(aa[0], aa[1]);  sta.y = pk2(aa[2], aa[3]);
            stb.x = pk2(ab[0], ab[1]);  stb.y = pk2(ab[2], ab[3]);
            *reinterpret_cast<ulonglong2*>(&sA[0][(o1 * 16 + o2) * 4]) = sta;
            *reinterpret_cast<ulonglong2*>(&sA[1][(o1 * 16 + o2) * 4]) = stb;
        }
        __syncthreads();

        // ---- step 2 (both slices, shared c1 loads): B[r1] per slice ----
        u64 acca[4][2], accb[4][2];
        #pragma unroll
        for (int r1 = 0; r1 < 4; r1++) {
            acca[r1][0] = 0ull; acca[r1][1] = 0ull;
            accb[r1][0] = 0ull; accb[r1][1] = 0ull;
        }
        #pragma unroll
        for (int i1 = 0; i1 < 16; i1++) {
            const ulonglong2 ava = *reinterpret_cast<const ulonglong2*>(
                &sA[0][(i1 * 16 + o2) * 4]);             // (r2 0,1),(r2 2,3)
            const ulonglong2 avb = *reinterpret_cast<const ulonglong2*>(
                &sA[1][(i1 * 16 + o2) * 4]);
            const ulonglong2* cp = reinterpret_cast<const ulonglong2*>(
                &sc1[(o1 * 16 + i1) * 16]);              // [r1][(r2 0,1),(r2 2,3)]
            #pragma unroll
            for (int r1 = 0; r1 < 4; r1++) {
                ulonglong2 c = cp[r1];
                acca[r1][0] = fma2(ava.x, c.x, acca[r1][0]);
                acca[r1][1] = fma2(ava.y, c.y, acca[r1][1]);
                accb[r1][0] = fma2(avb.x, c.x, accb[r1][0]);
                accb[r1][1] = fma2(avb.y, c.y, accb[r1][1]);
            }
        }
        u64 bda[4], bdb[4];
        #pragma unroll
        for (int r1 = 0; r1 < 4; r1++) {
            float ba = hadd(acca[r1][0]) + hadd(acca[r1][1]);
            float bb = hadd(accb[r1][0]) + hadd(accb[r1][1]);
            bda[r1] = pk2(ba, ba);
            bdb[r1] = pk2(bb, bb);
        }

        // ---- step 3 (both slices): y[o0-pair] += sum_r1 B[r1]*c0[i0,r1,o0] ----
        const ulonglong2* cqa = reinterpret_cast<const ulonglong2*>(&sc0[(2 * k + 0) * 128]);
        const ulonglong2* cqb = reinterpret_cast<const ulonglong2*>(&sc0[(2 * k + 1) * 128]);
        #pragma unroll
        for (int q = 0; q < 8; q++) {
            #pragma unroll
            for (int r1 = 0; r1 < 4; r1++) {
                ulonglong2 ca = cqa[r1 * 8 + q];         // o0 = 4q..4q+3
                ulonglong2 cb = cqb[r1 * 8 + q];
                yp[2 * q]     = fma2(bda[r1], ca.x, yp[2 * q]);
                yp[2 * q + 1] = fma2(bda[r1], ca.y, yp[2 * q + 1]);
                yp[2 * q]     = fma2(bdb[r1], cb.x, yp[2 * q]);
                yp[2 * q + 1] = fma2(bdb[r1], cb.y, yp[2 * q + 1]);
            }
        }

        // stage next pair's x (different parity buffers; race-free before sync)
        if (k < 7) {
            sX[1 - p][0][tid] = xn0;
            sX[1 - p][1][tid] = xn1;
        }
        __syncthreads();
    }

    // ---- write partial (coalesced) ----
    float* sp = g_scratch + ((size_t)(half * 128 + token) << 13);
    #pragma unroll
    for (int q = 0; q < 8; q++) {
        float f0, f1, f2, f3;
        unpk(yp[2 * q],     f0, f1);
        unpk(yp[2 * q + 1], f2, f3);
        sp[(4 * q + 0) * 256 + tid] = f0;
        sp[(4 * q + 1) * 256 + tid] = f1;
        sp[(4 * q + 2) * 256 + tid] = f2;
        sp[(4 * q + 3) * 256 + tid] = f3;
    }
}

__global__ __launch_bounds__(128)
void tt_reduce_kernel(const float* __restrict__ bias, float* __restrict__ out)
{
    // out = 262144 float4; grid 2048 x 128 thr, 1 float4/thread
    const int v = blockIdx.x * 128 + threadIdx.x;        // 0 .. 262143
    const float4* s = reinterpret_cast<const float4*>(g_scratch);
    const float4 a  = s[v];
    const float4 b  = s[v + (1 << 18)];
    const float4 bb = reinterpret_cast<const float4*>(bias)[v & 2047];
    float4 r;
    r.x = a.x + b.x + bb.x;
    r.y = a.y + b.y + bb.y;
    r.z = a.z + b.z + bb.z;
    r.w = a.w + b.w + bb.w;
    reinterpret_cast<float4*>(out)[v] = r;
}

extern "C" void kernel_launch(void* const* d_in, const int* in_sizes, int n_in,
                              void* d_out, int out_size)
{
    const float* x    = (const float*)d_in[0];  // [128, 8192]
    const float* g0   = (const float*)d_in[1];  // [1,32,32,4]
    const float* g1   = (const float*)d_in[2];  // [4,16,16,4]
    const float* g2   = (const float*)d_in[3];  // [4,16,16,1]
    const float* bias = (const float*)d_in[4];  // [8192]
    float* out = (float*)d_out;                 // [128, 8192]

    tt_partial_kernel<<<256, THREADS>>>(x, g0, g1, g2);
    tt_reduce_kernel<<<2048, 128>>>(bias, out);
}